// round 1
// baseline (speedup 1.0000x reference)
#include <cuda_runtime.h>
#include <cuda_bf16.h>

#define NPTS 4096
#define BATCH 8
#define KNBR 30
#define NEG_SLOPE 0.2f

// scratch: neighbor indices [B, N, 30]
__device__ int g_idx[BATCH * NPTS * KNBR];

__device__ __forceinline__ unsigned int fkey(float f) {
    unsigned int u = __float_as_uint(f);
    return (u & 0x80000000u) ? ~u : (u | 0x80000000u);
}

__device__ __forceinline__ float lrelu(float v) {
    return v > 0.0f ? v : NEG_SLOPE * v;
}

// ---------------------------------------------------------------------------
// Kernel 1: KNN (top-30 by pd = 2*inner - qq - cc, descending, ties -> low idx)
// grid: (128, 8)  block: 128 threads (4 warps), each warp handles 8 queries
// dynamic smem: xs[3*4096] floats + dump[4 warps * 32 lanes * 30] u64
// ---------------------------------------------------------------------------
__global__ void __launch_bounds__(128) knn_kernel(const float* __restrict__ x) {
    extern __shared__ unsigned char sm_raw[];
    float* xs = (float*)sm_raw;  // [3][4096]
    unsigned long long* dump = (unsigned long long*)(sm_raw + 3 * NPTS * 4);

    const int b = blockIdx.y;
    const int tid = threadIdx.x;
    const int wid = tid >> 5;
    const int lane = tid & 31;
    const float* xb = x + b * 3 * NPTS;

    for (int i = tid; i < 3 * NPTS; i += 128) xs[i] = xb[i];
    __syncthreads();

    const int qbase = blockIdx.x * 32;
    unsigned long long* dp = dump + (wid * 32 + lane) * KNBR;

    for (int t = 0; t < 8; ++t) {
        const int q = qbase + wid * 8 + t;
        const float qx = xs[q], qy = xs[NPTS + q], qz = xs[2 * NPTS + q];
        const float qq = qx * qx + qy * qy + qz * qz;

        unsigned long long lst[KNBR];
#pragma unroll
        for (int i = 0; i < KNBR; ++i) lst[i] = 0ull;

        for (int c = 0; c < NPTS / 32; ++c) {
            const int m = lane + (c << 5);
            const float cx = xs[m], cy = xs[NPTS + m], cz = xs[2 * NPTS + m];
            const float inner = qx * cx + qy * cy + qz * cz;
            const float cc = cx * cx + cy * cy + cz * cz;
            const float pd = 2.0f * inner - qq - cc;
            unsigned long long key =
                ((unsigned long long)fkey(pd) << 32) | (unsigned int)(0xFFFFFFFFu - (unsigned)m);
            if (key > lst[KNBR - 1]) {
#pragma unroll
                for (int i = 0; i < KNBR; ++i) {
                    if (key > lst[i]) { unsigned long long tmp = lst[i]; lst[i] = key; key = tmp; }
                }
            }
        }

#pragma unroll
        for (int i = 0; i < KNBR; ++i) dp[i] = lst[i];
        __syncwarp();

        int ptr = 0;
        const int obase = (b * NPTS + q) * KNBR;
        for (int r = 0; r < KNBR; ++r) {
            unsigned long long cand = (ptr < KNBR) ? dp[ptr] : 0ull;
            unsigned long long best = cand;
#pragma unroll
            for (int off = 16; off; off >>= 1) {
                unsigned long long o = __shfl_xor_sync(0xFFFFFFFFu, best, off);
                best = (o > best) ? o : best;
            }
            if (cand == best && cand != 0ull) ++ptr;
            if (lane == 0) g_idx[obase + r] = (int)(0xFFFFFFFFu - (unsigned int)best);
        }
        __syncwarp();
    }
}

// ---------------------------------------------------------------------------
// Kernel 2: fused edge-MLP + prefix online-softmax pooling
// One warp per point; each lane owns output channels (lane, lane+32).
// w2 rows held in registers (128 f32/lane); h1 broadcast via 64 f32 smem/warp.
// grid: 512 blocks, 256 threads (8 warps), 8 points per warp.
// ---------------------------------------------------------------------------
__global__ void __launch_bounds__(256, 1) mlp_kernel(
    const float* __restrict__ x,
    const float* __restrict__ w1, const float* __restrict__ g1, const float* __restrict__ b1,
    const float* __restrict__ w2, const float* __restrict__ g2, const float* __restrict__ b2,
    const float* __restrict__ wa, const float* __restrict__ ba,
    const float* __restrict__ ga, const float* __restrict__ bga,
    float* __restrict__ out)
{
    __shared__ float hs_all[8][64];
    const int tid = threadIdx.x;
    const int wid = tid >> 5;
    const int lane = tid & 31;
    float* hs = hs_all[wid];

    const float rs = rsqrtf(1.0f + 1e-5f);
    const int o0 = lane, o1 = lane + 32;

    float w1r0[6], w1r1[6];
#pragma unroll
    for (int i = 0; i < 6; ++i) { w1r0[i] = w1[o0 * 6 + i]; w1r1[i] = w1[o1 * 6 + i]; }

    float w2r0[64], w2r1[64];
#pragma unroll
    for (int i = 0; i < 64; ++i) { w2r0[i] = w2[o0 * 64 + i]; w2r1[i] = w2[o1 * 64 + i]; }

    const float s1_0 = g1[o0] * rs, s1_1 = g1[o1] * rs;
    const float bb1_0 = b1[o0],     bb1_1 = b1[o1];
    const float s2_0 = g2[o0] * rs, s2_1 = g2[o1] * rs;
    const float bb2_0 = b2[o0],     bb2_1 = b2[o1];
    const float wa0 = wa[o0], wa1 = wa[o1];
    const float ba0 = ba[0];
    const float sa = ga[0] * rs;
    const float bza = bga[0];

    for (int t = 0; t < 8; ++t) {
        const int p = blockIdx.x * 64 + wid * 8 + t;
        const int b = p >> 12;
        const int n = p & (NPTS - 1);
        const float* xb = x + b * 3 * NPTS;
        const float cx = xb[n], cy = xb[NPTS + n], cz = xb[2 * NPTS + n];

        const int myidx = (lane < KNBR) ? g_idx[(b * NPTS + n) * KNBR + lane] : 0;

        float num0 = 0.0f, num1 = 0.0f, den = 0.0f, mm = -1e30f;
        float acc0 = 0.0f, acc1 = 0.0f;

#pragma unroll 1
        for (int j = 0; j < KNBR; ++j) {
            const int nb = __shfl_sync(0xFFFFFFFFu, myidx, j);
            const float nx = xb[nb], ny = xb[NPTS + nb], nz = xb[2 * NPTS + nb];
            const float f0 = nx - cx, f1 = ny - cy, f2 = nz - cz;

            float h0 = w1r0[0] * f0;
            h0 = fmaf(w1r0[1], f1, h0); h0 = fmaf(w1r0[2], f2, h0);
            h0 = fmaf(w1r0[3], cx, h0); h0 = fmaf(w1r0[4], cy, h0);
            h0 = fmaf(w1r0[5], cz, h0);
            float h1v = w1r1[0] * f0;
            h1v = fmaf(w1r1[1], f1, h1v); h1v = fmaf(w1r1[2], f2, h1v);
            h1v = fmaf(w1r1[3], cx, h1v); h1v = fmaf(w1r1[4], cy, h1v);
            h1v = fmaf(w1r1[5], cz, h1v);
            h0  = lrelu(fmaf(h0,  s1_0, bb1_0));
            h1v = lrelu(fmaf(h1v, s1_1, bb1_1));

            hs[lane] = h0;
            hs[lane + 32] = h1v;
            __syncwarp();

            float a0 = 0.0f, a1 = 0.0f, a2 = 0.0f, a3 = 0.0f;
            const float4* h4 = (const float4*)hs;
#pragma unroll
            for (int q = 0; q < 16; ++q) {
                const float4 hv = h4[q];
                a0 = fmaf(w2r0[4 * q + 0], hv.x, a0);
                a0 = fmaf(w2r0[4 * q + 1], hv.y, a0);
                a2 = fmaf(w2r0[4 * q + 2], hv.z, a2);
                a2 = fmaf(w2r0[4 * q + 3], hv.w, a2);
                a1 = fmaf(w2r1[4 * q + 0], hv.x, a1);
                a1 = fmaf(w2r1[4 * q + 1], hv.y, a1);
                a3 = fmaf(w2r1[4 * q + 2], hv.z, a3);
                a3 = fmaf(w2r1[4 * q + 3], hv.w, a3);
            }
            __syncwarp();

            const float g0v = lrelu(fmaf(a0 + a2, s2_0, bb2_0));
            const float g1v = lrelu(fmaf(a1 + a3, s2_1, bb2_1));

            float ap = wa0 * g0v + wa1 * g1v;
#pragma unroll
            for (int off = 16; off; off >>= 1)
                ap += __shfl_xor_sync(0xFFFFFFFFu, ap, off);

            float av = lrelu(fmaf(ap + ba0, sa, bza));

            // online softmax (av warp-uniform -> no divergence)
            if (av > mm) {
                const float sc = __expf(mm - av);
                num0 *= sc; num1 *= sc; den *= sc;
                mm = av;
            }
            const float pj = __expf(av - mm);
            num0 = fmaf(pj, g0v, num0);
            num1 = fmaf(pj, g1v, num1);
            den += pj;

            if (j == 9 || j == 19 || j == 29) {
                const float idn = 1.0f / den;
                acc0 = fmaf(num0, idn, acc0);
                acc1 = fmaf(num1, idn, acc1);
            }
        }

        out[(b * 64 + o0) * NPTS + n] = acc0 * (1.0f / 3.0f);
        out[(b * 64 + o1) * NPTS + n] = acc1 * (1.0f / 3.0f);
    }
}

extern "C" void kernel_launch(void* const* d_in, const int* in_sizes, int n_in,
                              void* d_out, int out_size) {
    const float* x   = (const float*)d_in[0];
    const float* w1  = (const float*)d_in[1];
    const float* g1  = (const float*)d_in[2];
    const float* b1  = (const float*)d_in[3];
    const float* w2  = (const float*)d_in[4];
    const float* g2  = (const float*)d_in[5];
    const float* b2  = (const float*)d_in[6];
    const float* wa  = (const float*)d_in[7];
    const float* ba  = (const float*)d_in[8];
    const float* ga  = (const float*)d_in[9];
    const float* bga = (const float*)d_in[10];
    float* out = (float*)d_out;

    const int knn_smem = 3 * NPTS * 4 + 4 * 32 * KNBR * 8;  // 49152 + 30720
    cudaFuncSetAttribute(knn_kernel, cudaFuncAttributeMaxDynamicSharedMemorySize, knn_smem);

    knn_kernel<<<dim3(NPTS / 32, BATCH), 128, knn_smem>>>(x);
    mlp_kernel<<<(BATCH * NPTS) / 64, 256>>>(x, w1, g1, b1, w2, g2, b2,
                                             wa, ba, ga, bga, out);
}

// round 2
// speedup vs baseline: 1.5443x; 1.5443x over previous
#include <cuda_runtime.h>
#include <cuda_bf16.h>

#define NPTS 4096
#define BATCH 8
#define KNBR 30
#define NEG_SLOPE 0.2f

// scratch: neighbor indices [B, N, 30]
__device__ int g_idx[BATCH * NPTS * KNBR];

__device__ __forceinline__ unsigned int fkey(float f) {
    unsigned int u = __float_as_uint(f);
    unsigned int mask = (unsigned int)(((int)u) >> 31) | 0x80000000u;
    return u ^ mask;
}

__device__ __forceinline__ float lrelu(float v) {
    return v > 0.0f ? v : NEG_SLOPE * v;
}

__device__ __forceinline__ void insert30(unsigned long long (&lst)[KNBR],
                                         unsigned long long key) {
#pragma unroll
    for (int i = 0; i < KNBR; ++i) {
        unsigned long long mx = key > lst[i] ? key : lst[i];
        unsigned long long mn = key > lst[i] ? lst[i] : key;
        lst[i] = mx;
        key = mn;
    }
}

// ---------------------------------------------------------------------------
// Kernel 1: KNN — one THREAD per query, streaming register top-30.
// grid: (32, 8), block 128. smem: float4[4096] = 64KB (x,y,z,norm).
// ---------------------------------------------------------------------------
__global__ void __launch_bounds__(128) knn_kernel(const float* __restrict__ x) {
    extern __shared__ float4 p4[];
    const int b = blockIdx.y;
    const int tid = threadIdx.x;
    const float* xb = x + b * 3 * NPTS;

    for (int i = tid; i < NPTS; i += 128) {
        float cx = xb[i], cy = xb[NPTS + i], cz = xb[2 * NPTS + i];
        p4[i] = make_float4(cx, cy, cz, cx * cx + cy * cy + cz * cz);
    }
    __syncthreads();

    const int q = blockIdx.x * 128 + tid;
    const float4 qv = p4[q];
    const float qq = qv.w;

    unsigned long long lst[KNBR];
#pragma unroll
    for (int i = 0; i < KNBR; ++i) lst[i] = 0ull;

#pragma unroll 1
    for (int m = 0; m < NPTS; m += 2) {
        const float4 c0 = p4[m];
        const float4 c1 = p4[m + 1];
        float d0 = qv.x * c0.x;
        d0 = fmaf(qv.y, c0.y, d0);
        d0 = fmaf(qv.z, c0.z, d0);
        float d1 = qv.x * c1.x;
        d1 = fmaf(qv.y, c1.y, d1);
        d1 = fmaf(qv.z, c1.z, d1);
        const float pd0 = fmaf(2.0f, d0, -qq) - c0.w;
        const float pd1 = fmaf(2.0f, d1, -qq) - c1.w;
        const unsigned long long k0 =
            ((unsigned long long)fkey(pd0) << 32) | (unsigned int)(~m);
        const unsigned long long k1 =
            ((unsigned long long)fkey(pd1) << 32) | (unsigned int)(~(m + 1));
        const bool want = (k0 > lst[KNBR - 1]) || (k1 > lst[KNBR - 1]);
        if (__any_sync(0xFFFFFFFFu, want)) {
            if (k0 > lst[KNBR - 1]) insert30(lst, k0);
            if (k1 > lst[KNBR - 1]) insert30(lst, k1);
        }
    }

    const int obase = (b * NPTS + q) * KNBR;
#pragma unroll
    for (int i = 0; i < KNBR; ++i)
        g_idx[obase + i] = (int)(~(unsigned int)lst[i]);
}

// ---------------------------------------------------------------------------
// packed f32x2 helpers
// ---------------------------------------------------------------------------
__device__ __forceinline__ unsigned long long pack2(float lo, float hi) {
    unsigned long long r;
    asm("mov.b64 %0, {%1, %2};" : "=l"(r) : "f"(lo), "f"(hi));
    return r;
}
__device__ __forceinline__ void unpack2(unsigned long long v, float& lo, float& hi) {
    asm("mov.b64 {%0, %1}, %2;" : "=f"(lo), "=f"(hi) : "l"(v));
}
__device__ __forceinline__ unsigned long long fma2(unsigned long long a,
                                                   unsigned long long b,
                                                   unsigned long long c) {
    unsigned long long d;
    asm("fma.rn.f32x2 %0, %1, %2, %3;" : "=l"(d) : "l"(a), "l"(b), "l"(c));
    return d;
}
__device__ __forceinline__ unsigned long long add2(unsigned long long a,
                                                   unsigned long long b) {
    unsigned long long d;
    asm("add.rn.f32x2 %0, %1, %2;" : "=l"(d) : "l"(a), "l"(b));
    return d;
}

// ---------------------------------------------------------------------------
// Kernel 2: fused edge-MLP + prefix online-softmax pooling.
// One warp per point-group of 8; 2 channels per lane; w2 packed as f32x2
// pairs in registers; h1 stored DUPLICATED in smem so ulonglong2 loads give
// ready-packed {h,h} operands. Two points processed per iteration for ILP.
// ---------------------------------------------------------------------------
__global__ void __launch_bounds__(256, 1) mlp_kernel(
    const float* __restrict__ x,
    const float* __restrict__ w1, const float* __restrict__ g1, const float* __restrict__ b1,
    const float* __restrict__ w2, const float* __restrict__ g2, const float* __restrict__ b2,
    const float* __restrict__ wa, const float* __restrict__ ba,
    const float* __restrict__ ga, const float* __restrict__ bga,
    float* __restrict__ out)
{
    __shared__ __align__(16) unsigned long long hs_all[8][128];  // 2 pts x 64 dup-pairs
    const int tid = threadIdx.x;
    const int wid = tid >> 5;
    const int lane = tid & 31;
    unsigned long long* hsA = hs_all[wid];
    unsigned long long* hsB = hs_all[wid] + 64;

    const float rs = rsqrtf(1.0f + 1e-5f);
    const int o0 = lane, o1 = lane + 32;

    float w1r0[6], w1r1[6];
#pragma unroll
    for (int i = 0; i < 6; ++i) { w1r0[i] = w1[o0 * 6 + i]; w1r1[i] = w1[o1 * 6 + i]; }

    unsigned long long w2p[64];
#pragma unroll
    for (int i = 0; i < 64; ++i) w2p[i] = pack2(w2[o0 * 64 + i], w2[o1 * 64 + i]);

    const float s1_0 = g1[o0] * rs, s1_1 = g1[o1] * rs;
    const float bb1_0 = b1[o0],     bb1_1 = b1[o1];
    const float s2_0 = g2[o0] * rs, s2_1 = g2[o1] * rs;
    const float bb2_0 = b2[o0],     bb2_1 = b2[o1];
    const float wa0 = wa[o0], wa1 = wa[o1];
    const float ba0 = ba[0];
    const float sa = ga[0] * rs;
    const float bza = bga[0];

    const int pbase = blockIdx.x * 64 + wid * 8;

    for (int tt = 0; tt < 4; ++tt) {
        const int pA = pbase + tt;
        const int pB = pbase + tt + 4;
        const int bA = pA >> 12, nA = pA & (NPTS - 1);
        const int bB = pB >> 12, nB = pB & (NPTS - 1);
        const float* xA = x + bA * 3 * NPTS;
        const float* xB = x + bB * 3 * NPTS;
        const float cxA = xA[nA], cyA = xA[NPTS + nA], czA = xA[2 * NPTS + nA];
        const float cxB = xB[nB], cyB = xB[NPTS + nB], czB = xB[2 * NPTS + nB];

        const int idxA = (lane < KNBR) ? g_idx[(bA * NPTS + nA) * KNBR + lane] : 0;
        const int idxB = (lane < KNBR) ? g_idx[(bB * NPTS + nB) * KNBR + lane] : 0;

        float numA0 = 0.f, numA1 = 0.f, denA = 0.f, mmA = -1e30f, accA0 = 0.f, accA1 = 0.f;
        float numB0 = 0.f, numB1 = 0.f, denB = 0.f, mmB = -1e30f, accB0 = 0.f, accB1 = 0.f;

#pragma unroll 1
        for (int j = 0; j < KNBR; ++j) {
            const int nbA = __shfl_sync(0xFFFFFFFFu, idxA, j);
            const int nbB = __shfl_sync(0xFFFFFFFFu, idxB, j);
            const float fxA = xA[nbA] - cxA, fyA = xA[NPTS + nbA] - cyA, fzA = xA[2 * NPTS + nbA] - czA;
            const float fxB = xB[nbB] - cxB, fyB = xB[NPTS + nbB] - cyB, fzB = xB[2 * NPTS + nbB] - czB;

            // layer 1, two channels, both points
            float hA0 = w1r0[0] * fxA; hA0 = fmaf(w1r0[1], fyA, hA0); hA0 = fmaf(w1r0[2], fzA, hA0);
            hA0 = fmaf(w1r0[3], cxA, hA0); hA0 = fmaf(w1r0[4], cyA, hA0); hA0 = fmaf(w1r0[5], czA, hA0);
            float hA1 = w1r1[0] * fxA; hA1 = fmaf(w1r1[1], fyA, hA1); hA1 = fmaf(w1r1[2], fzA, hA1);
            hA1 = fmaf(w1r1[3], cxA, hA1); hA1 = fmaf(w1r1[4], cyA, hA1); hA1 = fmaf(w1r1[5], czA, hA1);
            float hB0 = w1r0[0] * fxB; hB0 = fmaf(w1r0[1], fyB, hB0); hB0 = fmaf(w1r0[2], fzB, hB0);
            hB0 = fmaf(w1r0[3], cxB, hB0); hB0 = fmaf(w1r0[4], cyB, hB0); hB0 = fmaf(w1r0[5], czB, hB0);
            float hB1 = w1r1[0] * fxB; hB1 = fmaf(w1r1[1], fyB, hB1); hB1 = fmaf(w1r1[2], fzB, hB1);
            hB1 = fmaf(w1r1[3], cxB, hB1); hB1 = fmaf(w1r1[4], cyB, hB1); hB1 = fmaf(w1r1[5], czB, hB1);
            hA0 = lrelu(fmaf(hA0, s1_0, bb1_0));
            hA1 = lrelu(fmaf(hA1, s1_1, bb1_1));
            hB0 = lrelu(fmaf(hB0, s1_0, bb1_0));
            hB1 = lrelu(fmaf(hB1, s1_1, bb1_1));

            __syncwarp();
            hsA[lane]      = pack2(hA0, hA0);
            hsA[lane + 32] = pack2(hA1, hA1);
            hsB[lane]      = pack2(hB0, hB0);
            hsB[lane + 32] = pack2(hB1, hB1);
            __syncwarp();

            // layer 2 mat-vec, packed f32x2, 4 rotating accumulators per point
            unsigned long long aA0 = 0ull, aA1 = 0ull, aA2 = 0ull, aA3 = 0ull;
            unsigned long long aB0 = 0ull, aB1 = 0ull, aB2 = 0ull, aB3 = 0ull;
            const ulonglong2* hA2p = (const ulonglong2*)hsA;
            const ulonglong2* hB2p = (const ulonglong2*)hsB;
#pragma unroll
            for (int q = 0; q < 32; q += 2) {
                const ulonglong2 vA0 = hA2p[q], vA1 = hA2p[q + 1];
                const ulonglong2 vB0 = hB2p[q], vB1 = hB2p[q + 1];
                aA0 = fma2(w2p[2 * q + 0], vA0.x, aA0);
                aA1 = fma2(w2p[2 * q + 1], vA0.y, aA1);
                aA2 = fma2(w2p[2 * q + 2], vA1.x, aA2);
                aA3 = fma2(w2p[2 * q + 3], vA1.y, aA3);
                aB0 = fma2(w2p[2 * q + 0], vB0.x, aB0);
                aB1 = fma2(w2p[2 * q + 1], vB0.y, aB1);
                aB2 = fma2(w2p[2 * q + 2], vB1.x, aB2);
                aB3 = fma2(w2p[2 * q + 3], vB1.y, aB3);
            }
            const unsigned long long sA = add2(add2(aA0, aA1), add2(aA2, aA3));
            const unsigned long long sB = add2(add2(aB0, aB1), add2(aB2, aB3));
            float uA0, uA1, uB0, uB1;
            unpack2(sA, uA0, uA1);
            unpack2(sB, uB0, uB1);

            const float gA0 = lrelu(fmaf(uA0, s2_0, bb2_0));
            const float gA1 = lrelu(fmaf(uA1, s2_1, bb2_1));
            const float gB0 = lrelu(fmaf(uB0, s2_0, bb2_0));
            const float gB1 = lrelu(fmaf(uB1, s2_1, bb2_1));

            float apA = fmaf(wa0, gA0, wa1 * gA1);
            float apB = fmaf(wa0, gB0, wa1 * gB1);
#pragma unroll
            for (int off = 16; off; off >>= 1) {
                apA += __shfl_xor_sync(0xFFFFFFFFu, apA, off);
                apB += __shfl_xor_sync(0xFFFFFFFFu, apB, off);
            }
            const float avA = lrelu(fmaf(apA + ba0, sa, bza));
            const float avB = lrelu(fmaf(apB + ba0, sa, bza));

            if (avA > mmA) {
                const float sc = __expf(mmA - avA);
                numA0 *= sc; numA1 *= sc; denA *= sc; mmA = avA;
            }
            const float pjA = __expf(avA - mmA);
            numA0 = fmaf(pjA, gA0, numA0);
            numA1 = fmaf(pjA, gA1, numA1);
            denA += pjA;

            if (avB > mmB) {
                const float sc = __expf(mmB - avB);
                numB0 *= sc; numB1 *= sc; denB *= sc; mmB = avB;
            }
            const float pjB = __expf(avB - mmB);
            numB0 = fmaf(pjB, gB0, numB0);
            numB1 = fmaf(pjB, gB1, numB1);
            denB += pjB;

            if (j == 9 || j == 19 || j == 29) {
                const float idnA = 1.0f / denA;
                const float idnB = 1.0f / denB;
                accA0 = fmaf(numA0, idnA, accA0);
                accA1 = fmaf(numA1, idnA, accA1);
                accB0 = fmaf(numB0, idnB, accB0);
                accB1 = fmaf(numB1, idnB, accB1);
            }
        }

        const float third = 1.0f / 3.0f;
        out[(bA * 64 + o0) * NPTS + nA] = accA0 * third;
        out[(bA * 64 + o1) * NPTS + nA] = accA1 * third;
        out[(bB * 64 + o0) * NPTS + nB] = accB0 * third;
        out[(bB * 64 + o1) * NPTS + nB] = accB1 * third;
    }
}

extern "C" void kernel_launch(void* const* d_in, const int* in_sizes, int n_in,
                              void* d_out, int out_size) {
    const float* x   = (const float*)d_in[0];
    const float* w1  = (const float*)d_in[1];
    const float* g1  = (const float*)d_in[2];
    const float* b1  = (const float*)d_in[3];
    const float* w2  = (const float*)d_in[4];
    const float* g2  = (const float*)d_in[5];
    const float* b2  = (const float*)d_in[6];
    const float* wa  = (const float*)d_in[7];
    const float* ba  = (const float*)d_in[8];
    const float* ga  = (const float*)d_in[9];
    const float* bga = (const float*)d_in[10];
    float* out = (float*)d_out;

    const int knn_smem = NPTS * 16;  // 64KB
    cudaFuncSetAttribute(knn_kernel, cudaFuncAttributeMaxDynamicSharedMemorySize, knn_smem);

    knn_kernel<<<dim3(NPTS / 128, BATCH), 128, knn_smem>>>(x);
    mlp_kernel<<<(BATCH * NPTS) / 64, 256>>>(x, w1, g1, b1, w2, g2, b2,
                                             wa, ba, ga, bga, out);
}

// round 3
// speedup vs baseline: 4.0243x; 2.6060x over previous
#include <cuda_runtime.h>
#include <cuda_bf16.h>

#define NPTS 4096
#define BATCH 8
#define KNBR 30
#define NEG_SLOPE 0.2f
#define FULL 0xFFFFFFFFu

typedef unsigned long long u64;

// scratch: neighbor indices [B, N, 30]
__device__ int g_idx[BATCH * NPTS * KNBR];

__device__ __forceinline__ unsigned int fkey(float f) {
    unsigned int u = __float_as_uint(f);
    unsigned int mask = (unsigned int)(((int)u) >> 31) | 0x80000000u;
    return u ^ mask;
}

__device__ __forceinline__ float lrelu(float v) {
    return v > 0.0f ? v : NEG_SLOPE * v;
}

__device__ __forceinline__ u64 pack2(float lo, float hi) {
    u64 r;
    asm("mov.b64 %0, {%1, %2};" : "=l"(r) : "f"(lo), "f"(hi));
    return r;
}
__device__ __forceinline__ void unpack2(u64 v, float& lo, float& hi) {
    asm("mov.b64 {%0, %1}, %2;" : "=f"(lo), "=f"(hi) : "l"(v));
}
__device__ __forceinline__ u64 fma2(u64 a, u64 b, u64 c) {
    u64 d;
    asm("fma.rn.f32x2 %0, %1, %2, %3;" : "=l"(d) : "l"(a), "l"(b), "l"(c));
    return d;
}
__device__ __forceinline__ u64 mul2(u64 a, u64 b) {
    u64 d;
    asm("mul.rn.f32x2 %0, %1, %2;" : "=l"(d) : "l"(a), "l"(b));
    return d;
}
__device__ __forceinline__ u64 add2(u64 a, u64 b) {
    u64 d;
    asm("add.rn.f32x2 %0, %1, %2;" : "=l"(d) : "l"(a), "l"(b));
    return d;
}
__device__ __forceinline__ u64 lrelu2(u64 v) {
    float lo, hi;
    unpack2(v, lo, hi);
    return pack2(lrelu(lo), lrelu(hi));
}

// ---------------------------------------------------------------------------
// Kernel 1: KNN — one WARP per query, warp-distributed sorted top-32 list
// (one u64 key per lane, descending; lane 29 = current 30th = threshold).
// Insert is warp-uniform: shfl_up + select. grid (32, 8), block 512.
// ---------------------------------------------------------------------------
__global__ void __launch_bounds__(512) knn_kernel(const float* __restrict__ x) {
    extern __shared__ float4 p4[];
    const int b = blockIdx.y;
    const int tid = threadIdx.x;
    const int wid = tid >> 5;
    const int lane = tid & 31;
    const float* xb = x + b * 3 * NPTS;

    for (int i = tid; i < NPTS; i += 512) {
        float cx = xb[i], cy = xb[NPTS + i], cz = xb[2 * NPTS + i];
        p4[i] = make_float4(cx, cy, cz, cx * cx + cy * cy + cz * cz);
    }
    __syncthreads();

    for (int t = 0; t < 8; ++t) {
        const int q = blockIdx.x * 128 + wid * 8 + t;
        const float4 qv = p4[q];
        const float qq = qv.w;

        u64 L = 0ull;  // distributed list element (lane i = i-th largest)

        for (int base = 0; base < NPTS; base += 32) {
            const int c = base + lane;
            const float4 cv = p4[c];
            float d = qv.x * cv.x;
            d = fmaf(qv.y, cv.y, d);
            d = fmaf(qv.z, cv.z, d);
            const float pd = fmaf(2.0f, d, -qq) - cv.w;
            const u64 key = ((u64)fkey(pd) << 32) | (unsigned int)(~c);

            const u64 thr = __shfl_sync(FULL, L, 29);
            unsigned m = __ballot_sync(FULL, key > thr);
            while (m) {
                const int src = __ffs(m) - 1;
                m &= m - 1;
                const u64 k = __shfl_sync(FULL, key, src);
                u64 prev = __shfl_up_sync(FULL, L, 1);
                if (lane == 0) prev = ~0ull;
                L = (L > k) ? L : ((prev > k) ? k : prev);
            }
        }

        if (lane < KNBR)
            g_idx[(b * NPTS + q) * KNBR + lane] = (int)(~(unsigned int)L);
        __syncwarp();
    }
}

// ---------------------------------------------------------------------------
// Kernel 2: fused edge-MLP + prefix-softmax pooling, lane-per-neighbor.
// Lane j owns neighbor j (j<30). Weights broadcast from smem (uniform addr).
// h1 kept packed f32x2 in registers; h2 written to padded smem buffer; one
// warp scan produces all three softmax denominators; single weighted
// per-channel reduction over j gives the output.
// ---------------------------------------------------------------------------
#define H2STRIDE 66

__global__ void __launch_bounds__(256, 2) mlp_kernel(
    const float* __restrict__ x,
    const float* __restrict__ w1, const float* __restrict__ g1, const float* __restrict__ b1,
    const float* __restrict__ w2, const float* __restrict__ g2, const float* __restrict__ b2,
    const float* __restrict__ wa, const float* __restrict__ ba,
    const float* __restrict__ ga, const float* __restrict__ bga,
    float* __restrict__ out)
{
    extern __shared__ __align__(16) unsigned char smraw[];
    u64*   w2p  = (u64*)smraw;                          // [64][32]  16384 B
    u64*   w1p  = (u64*)(smraw + 16384);                // [6][32]    1536 B
    u64*   s1p  = (u64*)(smraw + 17920);                // [32]        256 B
    u64*   b1p  = (u64*)(smraw + 18176);                // [32]        256 B
    float* s2v  = (float*)(smraw + 18432);              // [64]        256 B
    float* b2v  = (float*)(smraw + 18688);              // [64]        256 B
    float* wav  = (float*)(smraw + 18944);              // [64]        256 B
    float* wbuf = (float*)(smraw + 19200);              // [8][32]    1024 B
    float* h2b  = (float*)(smraw + 20224);              // [8][32][66] 67584 B

    const int tid = threadIdx.x;
    const int wid = tid >> 5;
    const int lane = tid & 31;
    const float rs = rsqrtf(1.0f + 1e-5f);

    if (tid < 192) {
        const int i = tid % 6, cp = tid / 6;
        w1p[i * 32 + cp] = pack2(w1[(2 * cp) * 6 + i], w1[(2 * cp + 1) * 6 + i]);
    }
    for (int idx = tid; idx < 2048; idx += 256) {
        const int c = idx >> 5, ip = idx & 31;
        w2p[c * 32 + ip] = pack2(w2[c * 64 + 2 * ip], w2[c * 64 + 2 * ip + 1]);
    }
    if (tid < 32) {
        s1p[tid] = pack2(g1[2 * tid] * rs, g1[2 * tid + 1] * rs);
        b1p[tid] = pack2(b1[2 * tid], b1[2 * tid + 1]);
    }
    if (tid >= 64 && tid < 128) {
        const int c = tid - 64;
        s2v[c] = g2[c] * rs;
        b2v[c] = b2[c];
        wav[c] = wa[c];
    }
    __syncthreads();

    const float ba0 = ba[0];
    const float sa = ga[0] * rs;
    const float bza = bga[0];
    float* h2w = h2b + wid * 32 * H2STRIDE;
    float* wrow = wbuf + wid * 32;

    for (int t = 0; t < 8; ++t) {
        const int p = blockIdx.x * 64 + wid * 8 + t;
        const int b = p >> 12, n = p & (NPTS - 1);
        const float* xb = x + b * 3 * NPTS;
        const float cx = xb[n], cy = xb[NPTS + n], cz = xb[2 * NPTS + n];
        const int nb = (lane < KNBR) ? g_idx[(b * NPTS + n) * KNBR + lane] : n;
        const float fx = xb[nb] - cx;
        const float fy = xb[NPTS + nb] - cy;
        const float fz = xb[2 * NPTS + nb] - cz;

        u64 f2[6];
        f2[0] = pack2(fx, fx); f2[1] = pack2(fy, fy); f2[2] = pack2(fz, fz);
        f2[3] = pack2(cx, cx); f2[4] = pack2(cy, cy); f2[5] = pack2(cz, cz);

        // layer 1: 64 channels packed as 32 f32x2 pairs per lane
        u64 h1p[32];
#pragma unroll
        for (int cp = 0; cp < 32; ++cp) {
            u64 a = mul2(w1p[0 * 32 + cp], f2[0]);
            a = fma2(w1p[1 * 32 + cp], f2[1], a);
            a = fma2(w1p[2 * 32 + cp], f2[2], a);
            a = fma2(w1p[3 * 32 + cp], f2[3], a);
            a = fma2(w1p[4 * 32 + cp], f2[4], a);
            a = fma2(w1p[5 * 32 + cp], f2[5], a);
            a = fma2(a, s1p[cp], b1p[cp]);
            h1p[cp] = lrelu2(a);
        }

        // layer 2: 64-channel matvec, w2 broadcast from smem
        float aj = 0.0f;
#pragma unroll 4
        for (int c = 0; c < 64; ++c) {
            const ulonglong2* wr = (const ulonglong2*)(w2p + c * 32);
            u64 a0 = 0ull, a1 = 0ull;
#pragma unroll
            for (int q8 = 0; q8 < 16; ++q8) {
                const ulonglong2 wv = wr[q8];
                a0 = fma2(wv.x, h1p[2 * q8], a0);
                a1 = fma2(wv.y, h1p[2 * q8 + 1], a1);
            }
            float lo, hi;
            unpack2(add2(a0, a1), lo, hi);
            const float h2c = lrelu(fmaf(lo + hi, s2v[c], b2v[c]));
            h2w[lane * H2STRIDE + c] = h2c;
            aj = fmaf(wav[c], h2c, aj);
        }

        // attention logit per lane(=neighbor)
        aj = lrelu(fmaf(aj + ba0, sa, bza));
        if (lane >= KNBR) aj = -1e30f;
        float mx = aj;
#pragma unroll
        for (int off = 16; off; off >>= 1)
            mx = fmaxf(mx, __shfl_xor_sync(FULL, mx, off));
        const float e = __expf(aj - mx);

        // inclusive scan for prefix denominators at k=10,20,30
        float scn = e;
#pragma unroll
        for (int off = 1; off < 32; off <<= 1) {
            const float v = __shfl_up_sync(FULL, scn, off);
            if (lane >= off) scn += v;
        }
        const float d10 = __shfl_sync(FULL, scn, 9);
        const float d20 = __shfl_sync(FULL, scn, 19);
        const float d30 = __shfl_sync(FULL, scn, 29);
        float ws = 0.0f;
        if (lane < 10) ws += 1.0f / d10;
        if (lane < 20) ws += 1.0f / d20;
        if (lane < 30) ws += 1.0f / d30;
        wrow[lane] = e * ws * (1.0f / 3.0f);
        __syncwarp();

        // weighted pooled output: lane owns channels (2*lane, 2*lane+1)
        u64 acc = 0ull;
#pragma unroll
        for (int j = 0; j < KNBR; ++j) {
            const float Wj = wrow[j];
            const u64 h = *(const u64*)&h2w[j * H2STRIDE + 2 * lane];
            acc = fma2(pack2(Wj, Wj), h, acc);
        }
        float v0, v1;
        unpack2(acc, v0, v1);
        out[(b * 64 + 2 * lane) * NPTS + n] = v0;
        out[(b * 64 + 2 * lane + 1) * NPTS + n] = v1;
        __syncwarp();
    }
}

extern "C" void kernel_launch(void* const* d_in, const int* in_sizes, int n_in,
                              void* d_out, int out_size) {
    const float* x   = (const float*)d_in[0];
    const float* w1  = (const float*)d_in[1];
    const float* g1  = (const float*)d_in[2];
    const float* b1  = (const float*)d_in[3];
    const float* w2  = (const float*)d_in[4];
    const float* g2  = (const float*)d_in[5];
    const float* b2  = (const float*)d_in[6];
    const float* wa  = (const float*)d_in[7];
    const float* ba  = (const float*)d_in[8];
    const float* ga  = (const float*)d_in[9];
    const float* bga = (const float*)d_in[10];
    float* out = (float*)d_out;

    const int knn_smem = NPTS * 16;  // 64KB
    cudaFuncSetAttribute(knn_kernel, cudaFuncAttributeMaxDynamicSharedMemorySize, knn_smem);
    const int mlp_smem = 20224 + 8 * 32 * H2STRIDE * 4;  // 87808 B
    cudaFuncSetAttribute(mlp_kernel, cudaFuncAttributeMaxDynamicSharedMemorySize, mlp_smem);

    knn_kernel<<<dim3(NPTS / 128, BATCH), 512, knn_smem>>>(x);
    mlp_kernel<<<(BATCH * NPTS) / 64, 256, mlp_smem>>>(x, w1, g1, b1, w2, g2, b2,
                                                       wa, ba, ga, bga, out);
}